// round 14
// baseline (speedup 1.0000x reference)
#include <cuda_runtime.h>
#include <cuda_fp16.h>
#include <cstdint>
#include <math.h>

#define B_  4
#define S_  2048
#define D_  1024
#define H_  16
#define HD_ 64
#define F_  4096
#define M_  (B_ * S_)   // 8192
#define MD_ ((size_t)M_ * D_)

#define SWZ(o) ((o) ^ (((o) >> 3) & 0x70))

// ---------------- scratch (static device globals; no allocation) ----------
__device__ __half g_xn [MD_];
__device__ __half g_qkv[3 * MD_];   // [q|k|v] fp16 single-plane
__device__ float g_bqkv[3 * D_];
__device__ __half g_ctx[MD_];
__device__ float g_res[MD_];
__device__ __half g_h1 [(size_t)M_ * F_];
#define WPOOL_ (4 * (size_t)D_ * D_ + 2 * (size_t)F_ * D_)
__device__ __half g_w[WPOOL_];

// ---------------- PTX helpers ---------------------------------------------
static __device__ __forceinline__ uint32_t smem_u32(const void* p) {
    uint32_t a;
    asm("{ .reg .u64 t; cvta.to.shared.u64 t, %1; cvt.u32.u64 %0, t; }"
        : "=r"(a) : "l"(p));
    return a;
}

#define CP16(dst, src) \
    asm volatile("cp.async.cg.shared.global [%0], [%1], 16;" \
                 :: "r"(dst), "l"(src) : "memory")
#define CP_COMMIT() asm volatile("cp.async.commit_group;" ::: "memory")
#define CP_WAIT0()  asm volatile("cp.async.wait_group 0;" ::: "memory")
#define CP_WAIT1()  asm volatile("cp.async.wait_group 1;" ::: "memory")

#define LDSM_X4(r0, r1, r2, r3, addr) \
    asm volatile("ldmatrix.sync.aligned.m8n8.x4.shared.b16 {%0,%1,%2,%3}, [%4];" \
                 : "=r"(r0), "=r"(r1), "=r"(r2), "=r"(r3) : "r"(addr))
#define LDSM_X4T(r0, r1, r2, r3, addr) \
    asm volatile("ldmatrix.sync.aligned.m8n8.x4.trans.shared.b16 {%0,%1,%2,%3}, [%4];" \
                 : "=r"(r0), "=r"(r1), "=r"(r2), "=r"(r3) : "r"(addr))

static __device__ __forceinline__ void mma_f16(float* c, const uint32_t* a,
                                               const uint32_t* b) {
    asm volatile(
        "mma.sync.aligned.m16n8k16.row.col.f32.f16.f16.f32 "
        "{%0,%1,%2,%3}, {%4,%5,%6,%7}, {%8,%9}, {%0,%1,%2,%3};"
        : "+f"(c[0]), "+f"(c[1]), "+f"(c[2]), "+f"(c[3])
        : "r"(a[0]), "r"(a[1]), "r"(a[2]), "r"(a[3]), "r"(b[0]), "r"(b[1]));
}

static __device__ __forceinline__ uint32_t pack_h2(float a, float b) {
    __half2 t = __floats2half2_rn(a, b);
    return *(uint32_t*)&t;
}

static __device__ __forceinline__ uint32_t ex2_h2(uint32_t x) {
    uint32_t y;
    asm("ex2.approx.f16x2 %0, %1;" : "=r"(y) : "r"(x));
    return y;
}

// ---------------- fused weight convert (fp16) + bias pool ------------------
__global__ __launch_bounds__(256) void split_all(const float* __restrict__ Wq,
                                                 const float* __restrict__ Wk,
                                                 const float* __restrict__ Wv,
                                                 const float* __restrict__ Wo,
                                                 const float* __restrict__ W1,
                                                 const float* __restrict__ W2,
                                                 const float* __restrict__ bq,
                                                 const float* __restrict__ bk,
                                                 const float* __restrict__ bv,
                                                 float* __restrict__ bpool,
                                                 __half* __restrict__ w16) {
    const size_t DD4 = (size_t)D_ * D_ / 4;
    const size_t FD4 = (size_t)F_ * D_ / 4;
    const size_t total4 = 4 * DD4 + 2 * FD4;
    size_t gtid = (size_t)blockIdx.x * 256 + threadIdx.x;
    if (gtid < 768) {
        float4 v = (gtid < 256) ? ((const float4*)bq)[gtid]
                 : (gtid < 512) ? ((const float4*)bk)[gtid - 256]
                                : ((const float4*)bv)[gtid - 512];
        ((float4*)bpool)[gtid] = v;
    }
    size_t i = gtid;
    size_t stride = (size_t)gridDim.x * 256;
    for (; i < total4; i += stride) {
        const float4* src;
        size_t j = i;
        if (j < 4 * DD4) {
            int w = (int)(j / DD4);
            j -= (size_t)w * DD4;
            src = (const float4*)(w == 0 ? Wq : w == 1 ? Wk : w == 2 ? Wv : Wo) + j;
        } else {
            j -= 4 * DD4;
            if (j < FD4) src = (const float4*)W1 + j;
            else         src = (const float4*)W2 + (j - FD4);
        }
        float4 v = *src;
        ((__half2*)w16)[i * 2 + 0] = __floats2half2_rn(v.x, v.y);
        ((__half2*)w16)[i * 2 + 1] = __floats2half2_rn(v.z, v.w);
    }
}

// ---------------- LayerNorm -> fp16 single plane ---------------------------
__global__ __launch_bounds__(256) void ln_kernel(const float* __restrict__ x,
                                                 const float* __restrict__ gw,
                                                 const float* __restrict__ bw,
                                                 __half* __restrict__ o16) {
    int row = blockIdx.x;
    int tid = threadIdx.x;
    const float4* xr = (const float4*)(x + (size_t)row * D_);
    float4 v = xr[tid];

    __shared__ float ws[8];
    __shared__ float sstat;
    int lane = tid & 31, wid = tid >> 5;

    float s = v.x + v.y + v.z + v.w;
#pragma unroll
    for (int o = 16; o; o >>= 1) s += __shfl_xor_sync(0xffffffffu, s, o);
    if (lane == 0) ws[wid] = s;
    __syncthreads();
    if (tid == 0) {
        float t = 0.f;
#pragma unroll
        for (int i = 0; i < 8; i++) t += ws[i];
        sstat = t * (1.0f / D_);
    }
    __syncthreads();
    float mu = sstat;

    float4 d;
    d.x = v.x - mu; d.y = v.y - mu; d.z = v.z - mu; d.w = v.w - mu;
    float s2 = d.x*d.x + d.y*d.y + d.z*d.z + d.w*d.w;
#pragma unroll
    for (int o = 16; o; o >>= 1) s2 += __shfl_xor_sync(0xffffffffu, s2, o);
    if (lane == 0) ws[wid] = s2;
    __syncthreads();
    if (tid == 0) {
        float t = 0.f;
#pragma unroll
        for (int i = 0; i < 8; i++) t += ws[i];
        sstat = rsqrtf(t * (1.0f / D_) + 1e-6f);
    }
    __syncthreads();
    float rstd = sstat;

    float4 gv = ((const float4*)gw)[tid];
    float4 bv = ((const float4*)bw)[tid];
    float o0 = d.x * rstd * gv.x + bv.x;
    float o1 = d.y * rstd * gv.y + bv.y;
    float o2 = d.z * rstd * gv.z + bv.z;
    float o3 = d.w * rstd * gv.w + bv.w;

    size_t base = (size_t)row * D_ + tid * 4;
    *(__half2*)(o16 + base)     = __floats2half2_rn(o0, o1);
    *(__half2*)(o16 + base + 2) = __floats2half2_rn(o2, o3);
}

// ---------------- mma.sync fp16 GEMM: C = A @ B^T --------------------------
// Block 128x128, 4 warps (2m x 2n), warp tile 64x64, 2 CTAs/SM, BK=64.
// Stage 32KB: A[16K] B[16K]; 3-stage cp.async pipeline, 1 sync per slab.
// EPI: 1 = fp32 +bias+res; 2 = gelu(+bias) -> fp16;
//      3 = fused QKV epilogue -> fp16 pool (Q scaled 0.125*log2e)
__device__ __forceinline__ float gelu_exact(float x) {
    return 0.5f * x * (1.0f + erff(x * 0.70710678118654752f));
}

#define QSCALE_ 0.18033688011112042f   // 0.125 * log2(e)

#define STAGE_ 32768
#define GEMM_SMEM (3 * STAGE_)

template<int EPI>
__global__ __launch_bounds__(128, 2)
void gemm_tc(const __half* __restrict__ A, const __half* __restrict__ Bm,
             const float* __restrict__ bias, const float* __restrict__ res,
             float* __restrict__ outF, __half* __restrict__ o16,
             int N, int K) {
    extern __shared__ char sm[];
    uint32_t smb = smem_u32(sm);
    int tid = threadIdx.x, lane = tid & 31, warp = tid >> 5;   // 4 warps
    int wm = warp & 1;          // rows wm*64
    int wn = warp >> 1;         // cols wn*64
    int bm = blockIdx.y * 128, bn = blockIdx.x * 128;

    const size_t rs = (size_t)K * 2;
    int lrow = tid >> 3;        // 0..15 base row (of 8-seg groups)
    int lseg = tid & 7;
    const char* gA = (const char*)A  + (size_t)(bm + lrow) * rs + lseg * 16;
    const char* gB = (const char*)Bm + (size_t)(bn + lrow) * rs + lseg * 16;

    float acc[4][8][4];
#pragma unroll
    for (int i = 0; i < 4; i++)
#pragma unroll
        for (int j = 0; j < 8; j++)
#pragma unroll
            for (int r = 0; r < 4; r++) acc[i][j][r] = 0.f;

    int nk = K >> 6;   // BK = 64

    auto load_slab = [&](int t) {
        uint32_t st = smb + (t % 3) * STAGE_;
        size_t gofs = (size_t)t * 128;
#pragma unroll
        for (int r = 0; r < 8; r++) {
            uint32_t dsw = SWZ((uint32_t)((lrow + r * 16) * 128 + lseg * 16));
            size_t so = (size_t)(r * 16) * rs + gofs;
            CP16(st + dsw,         gA + so);
            CP16(st + 16384 + dsw, gB + so);
        }
        CP_COMMIT();
    };

    load_slab(0);
    load_slab(1);

    int a_row = ((lane >> 3) & 1) * 8 + (lane & 7);
    int a_seg = lane >> 4;
    int b_row = (lane & 7) + ((lane >> 4) << 3);
    int b_seg = (lane >> 3) & 1;

    for (int t = 0; t < nk; t++) {
        if (t + 1 < nk) { CP_WAIT1(); } else { CP_WAIT0(); }
        __syncthreads();
        if (t + 2 < nk) load_slab(t + 2);

        uint32_t sa = smb + (t % 3) * STAGE_;
#pragma unroll
        for (int kk = 0; kk < 4; kk++) {
            uint32_t af[4][4];
#pragma unroll
            for (int mt = 0; mt < 4; mt++) {
                int row = wm * 64 + mt * 16 + a_row;
                uint32_t off = SWZ((uint32_t)(row * 128 + (kk * 2 + a_seg) * 16));
                LDSM_X4(af[mt][0], af[mt][1], af[mt][2], af[mt][3], sa + off);
            }
#pragma unroll
            for (int np = 0; np < 4; np++) {
                int row = wn * 64 + np * 16 + b_row;
                uint32_t off = SWZ((uint32_t)(row * 128 + (kk * 2 + b_seg) * 16));
                uint32_t b4[4];
                LDSM_X4(b4[0], b4[1], b4[2], b4[3], sa + 16384 + off);
#pragma unroll
                for (int mt = 0; mt < 4; mt++) {
                    mma_f16(acc[mt][2 * np],     af[mt], b4);
                    mma_f16(acc[mt][2 * np + 1], af[mt], b4 + 2);
                }
            }
        }
    }

    int r0 = lane >> 2;
    int c0 = (lane & 3) * 2;
#pragma unroll
    for (int mt = 0; mt < 4; mt++) {
#pragma unroll
        for (int nt = 0; nt < 8; nt++) {
            int grow = bm + wm * 64 + mt * 16 + r0;
            int gcol = bn + wn * 64 + nt * 8 + c0;
            float* a4 = acc[mt][nt];
#pragma unroll
            for (int half_ = 0; half_ < 2; half_++) {
                int rr = grow + half_ * 8;
                float v0 = a4[half_ * 2 + 0] + bias[gcol + 0];
                float v1 = a4[half_ * 2 + 1] + bias[gcol + 1];
                if (EPI == 1) {
                    size_t gi = (size_t)rr * N + gcol;
                    float2 rv = *(const float2*)&res[gi];
                    *(float2*)&outF[gi] = make_float2(v0 + rv.x, v1 + rv.y);
                } else if (EPI == 2) {
                    size_t gi = (size_t)rr * N + gcol;
                    *(__half2*)&o16[gi] =
                        __floats2half2_rn(gelu_exact(v0), gelu_exact(v1));
                } else {
                    int w = gcol >> 10;
                    int col = gcol & 1023;
                    float sc = (w == 0) ? QSCALE_ : 1.0f;
                    size_t base = (size_t)w * MD_ + (size_t)rr * D_ + col;
                    *(__half2*)&o16[base] = __floats2half2_rn(v0 * sc, v1 * sc);
                }
            }
        }
    }
}

// ---------------- tensor-core flash attention ------------------------------
// 4 warps x 32 q-rows. Streaming per-16-key block. Softmax via f16x2 exp2;
// row-sums l accumulated by an extra MMA against an all-ones B fragment.
// SMEM: Q 16KB @0; 2 stages of [K|V] 32KB @16384. (80KB -> 2 CTAs/SM)
#define ATT_STAGE 32768
#define ATT_SMEM  (16384 + 2 * ATT_STAGE)

static __device__ __forceinline__ void cp_plane128(uint32_t dst, const char* src,
                                                   int tid) {
#pragma unroll
    for (int i = 0; i < 8; i++) {
        int slot = tid + i * 128;
        int row = slot >> 3, seg = slot & 7;
        CP16(dst + SWZ((uint32_t)(row * 128 + seg * 16)),
             src + (size_t)row * (D_ * 2) + seg * 16);
    }
}

__global__ __launch_bounds__(128, 2)
void attn_tc(const __half* __restrict__ qkv, __half* __restrict__ ctx) {
    extern __shared__ char sm[];
    uint32_t smb = smem_u32(sm);
    int tid = threadIdx.x, lane = tid & 31, warp = tid >> 5;   // 4 warps
    int h = blockIdx.y, b = blockIdx.z;
    int q0 = blockIdx.x * 128;
    size_t bS = (size_t)b * S_;
    size_t hoff = (size_t)h * HD_;

    const __half* q_g = qkv;
    const __half* k_g = qkv + MD_;
    const __half* v_g = qkv + 2 * MD_;

    auto load_kv = [&](int t) {
        uint32_t st = smb + 16384 + (t & 1) * ATT_STAGE;
        size_t ro = (bS + (size_t)t * 128) * D_ + hoff;
        cp_plane128(st,         (const char*)(k_g + ro), tid);
        cp_plane128(st + 16384, (const char*)(v_g + ro), tid);
        CP_COMMIT();
    };

    cp_plane128(smb, (const char*)(q_g + (bS + q0) * D_ + hoff), tid);
    CP_COMMIT();
    load_kv(0);
    CP_WAIT0();
    __syncthreads();

    int a_row = ((lane >> 3) & 1) * 8 + (lane & 7);
    int a_seg = lane >> 4;
    uint32_t qf[2][4][4];   // [row-group][kk][frag]
#pragma unroll
    for (int g = 0; g < 2; g++)
#pragma unroll
        for (int kk = 0; kk < 4; kk++) {
            uint32_t off = SWZ((uint32_t)((warp * 32 + g * 16 + a_row) * 128 +
                                          (kk * 2 + a_seg) * 16));
            LDSM_X4(qf[g][kk][0], qf[g][kk][1], qf[g][kk][2], qf[g][kk][3],
                    smb + off);
        }
    load_kv(1);

    float O[2][8][4];
#pragma unroll
    for (int g = 0; g < 2; g++)
#pragma unroll
        for (int i = 0; i < 8; i++)
#pragma unroll
            for (int j = 0; j < 4; j++) O[g][i][j] = 0.f;
    float lacc[2][4];
#pragma unroll
    for (int g = 0; g < 2; g++)
#pragma unroll
        for (int j = 0; j < 4; j++) lacc[g][j] = 0.f;

    const uint32_t bones[2] = {0x3C003C00u, 0x3C003C00u};   // all ones (fp16)

    int b_row = lane & 7, b_seg = (lane >> 3) & 1, b_t = lane >> 4;
    int v_row = ((lane >> 3) & 1) * 8 + (lane & 7), v_t = lane >> 4;

    for (int t = 0; t < S_ / 128; t++) {
        if (t > 0) {
            CP_WAIT0();
            __syncthreads();
            if (t + 1 < S_ / 128) load_kv(t + 1);
        }

        uint32_t sa = smb + 16384 + (t & 1) * ATT_STAGE;

#pragma unroll
        for (int tp = 0; tp < 8; tp++) {      // 16-key block
            float s[2][2][4];
#pragma unroll
            for (int g = 0; g < 2; g++)
#pragma unroll
                for (int hh = 0; hh < 2; hh++)
#pragma unroll
                    for (int j = 0; j < 4; j++) s[g][hh][j] = 0.f;

#pragma unroll
            for (int kk = 0; kk < 4; kk++) {
                uint32_t off = SWZ((uint32_t)((tp * 16 + b_t * 8 + b_row) * 128 +
                                              (kk * 2 + b_seg) * 16));
                uint32_t k4[4];
                LDSM_X4(k4[0], k4[1], k4[2], k4[3], sa + off);
                mma_f16(s[0][0], qf[0][kk], k4);
                mma_f16(s[0][1], qf[0][kk], k4 + 2);
                mma_f16(s[1][0], qf[1][kk], k4);
                mma_f16(s[1][1], qf[1][kk], k4 + 2);
            }

            uint32_t AP[2][4];
#pragma unroll
            for (int g = 0; g < 2; g++) {
#pragma unroll
                for (int hh = 0; hh < 2; hh++) {
                    AP[g][hh * 2 + 0] = ex2_h2(pack_h2(s[g][hh][0], s[g][hh][1]));
                    AP[g][hh * 2 + 1] = ex2_h2(pack_h2(s[g][hh][2], s[g][hh][3]));
                }
            }
            mma_f16(lacc[0], AP[0], bones);
            mma_f16(lacc[1], AP[1], bones);

#pragma unroll
            for (int tpv = 0; tpv < 4; tpv++) {
                uint32_t off = SWZ((uint32_t)((tp * 16 + v_row) * 128 +
                                              (2 * tpv + v_t) * 16));
                uint32_t v4[4];
                LDSM_X4T(v4[0], v4[1], v4[2], v4[3], sa + 16384 + off);
                mma_f16(O[0][2 * tpv],     AP[0], v4);
                mma_f16(O[0][2 * tpv + 1], AP[0], v4 + 2);
                mma_f16(O[1][2 * tpv],     AP[1], v4);
                mma_f16(O[1][2 * tpv + 1], AP[1], v4 + 2);
            }
        }
    }

#pragma unroll
    for (int g = 0; g < 2; g++) {
        float inv0 = 1.f / lacc[g][0];
        float inv1 = 1.f / lacc[g][2];

        int rg0 = q0 + warp * 32 + g * 16 + (lane >> 2);
        int cbase = (int)hoff + (lane & 3) * 2;
#pragma unroll
        for (int tp = 0; tp < 8; tp++) {
            int cg = cbase + tp * 8;
            size_t i0 = (bS + rg0) * D_ + cg;
            size_t i1 = (bS + rg0 + 8) * D_ + cg;
            *(__half2*)&ctx[i0] =
                __floats2half2_rn(O[g][tp][0] * inv0, O[g][tp][1] * inv0);
            *(__half2*)&ctx[i1] =
                __floats2half2_rn(O[g][tp][2] * inv1, O[g][tp][3] * inv1);
        }
    }
}

// ---------------- launcher -------------------------------------------------
extern "C" void kernel_launch(void* const* d_in, const int* in_sizes, int n_in,
                              void* d_out, int out_size) {
    const float* x    = (const float*)d_in[0];
    const float* Wq   = (const float*)d_in[1];
    const float* bq   = (const float*)d_in[2];
    const float* Wk   = (const float*)d_in[3];
    const float* bk   = (const float*)d_in[4];
    const float* Wv   = (const float*)d_in[5];
    const float* bv   = (const float*)d_in[6];
    const float* Wo   = (const float*)d_in[7];
    const float* bo   = (const float*)d_in[8];
    const float* W1   = (const float*)d_in[9];
    const float* b1   = (const float*)d_in[10];
    const float* W2   = (const float*)d_in[11];
    const float* b2   = (const float*)d_in[12];
    const float* ln1g = (const float*)d_in[13];
    const float* ln1b = (const float*)d_in[14];
    const float* ln2g = (const float*)d_in[15];
    const float* ln2b = (const float*)d_in[16];
    float* out = (float*)d_out;

    __half *xn, *qkv, *ctx, *h1, *w16;
    float *resb, *bqkv;
    cudaGetSymbolAddress((void**)&xn,   g_xn);
    cudaGetSymbolAddress((void**)&qkv,  g_qkv);
    cudaGetSymbolAddress((void**)&bqkv, g_bqkv);
    cudaGetSymbolAddress((void**)&ctx,  g_ctx);
    cudaGetSymbolAddress((void**)&resb, g_res);
    cudaGetSymbolAddress((void**)&h1,   g_h1);
    cudaGetSymbolAddress((void**)&w16,  g_w);

    const size_t DD = (size_t)D_ * D_;
    const size_t FD = (size_t)F_ * D_;
    __half *wqkv = w16;                  // 3072 x 1024
    __half *wo = w16 + 3 * DD;
    __half *w1 = w16 + 4 * DD;
    __half *w2 = w16 + 4 * DD + FD;

    cudaFuncSetAttribute(gemm_tc<1>, cudaFuncAttributeMaxDynamicSharedMemorySize, GEMM_SMEM);
    cudaFuncSetAttribute(gemm_tc<2>, cudaFuncAttributeMaxDynamicSharedMemorySize, GEMM_SMEM);
    cudaFuncSetAttribute(gemm_tc<3>, cudaFuncAttributeMaxDynamicSharedMemorySize, GEMM_SMEM);
    cudaFuncSetAttribute(attn_tc,    cudaFuncAttributeMaxDynamicSharedMemorySize, ATT_SMEM);

    dim3 gQKV(3072 / 128, M_ / 128);  // (24, 64) = 1536 CTAs
    dim3 gD(D_ / 128, M_ / 128);      // (8, 64)  = 512
    dim3 gF(F_ / 128, M_ / 128);      // (32, 64) = 2048

    // 1) fused weight convert + bias pool
    split_all<<<4096, 256>>>(Wq, Wk, Wv, Wo, W1, W2, bq, bk, bv, bqkv, w16);
    // 2) ln1 -> xn fp16
    ln_kernel<<<M_, 256>>>(x, ln1g, ln1b, xn);
    // 3) fused QKV projection -> fp16 pool (Q scaled log2e/8)
    gemm_tc<3><<<gQKV, 128, GEMM_SMEM>>>(xn, wqkv, bqkv, nullptr,
                                         nullptr, qkv, 3072, D_);
    // 4) attention -> ctx fp16
    attn_tc<<<dim3(S_ / 128, H_, B_), 128, ATT_SMEM>>>(qkv, ctx);
    // 5) O projection + residual(x) -> resb fp32
    gemm_tc<1><<<gD, 128, GEMM_SMEM>>>(ctx, wo, bo, x, resb, nullptr, D_, D_);
    // 6) ln2 -> xn fp16
    ln_kernel<<<M_, 256>>>(resb, ln2g, ln2b, xn);
    // 7) MLP up + exact gelu -> h1 fp16
    gemm_tc<2><<<gF, 128, GEMM_SMEM>>>(xn, w1, b1, nullptr, nullptr, h1, F_, D_);
    // 8) MLP down + residual(resb) -> out fp32
    gemm_tc<1><<<gD, 128, GEMM_SMEM>>>(h1, w2, b2, resb, out, nullptr, D_, F_);
}

// round 15
// speedup vs baseline: 1.0252x; 1.0252x over previous
#include <cuda_runtime.h>
#include <cuda_fp16.h>
#include <cstdint>
#include <math.h>

#define B_  4
#define S_  2048
#define D_  1024
#define H_  16
#define HD_ 64
#define F_  4096
#define M_  (B_ * S_)   // 8192
#define MD_ ((size_t)M_ * D_)

#define SWZ(o) ((o) ^ (((o) >> 3) & 0x70))

// ---------------- scratch (static device globals; no allocation) ----------
__device__ __half g_xn [MD_];
__device__ __half g_qkv[3 * MD_];   // [q|k|v] fp16 single-plane
__device__ float g_bqkv[3 * D_];
__device__ __half g_ctx[MD_];
__device__ float g_res[MD_];
__device__ __half g_h1 [(size_t)M_ * F_];
#define WPOOL_ (4 * (size_t)D_ * D_ + 2 * (size_t)F_ * D_)
__device__ __half g_w[WPOOL_];

// ---------------- PTX helpers ---------------------------------------------
static __device__ __forceinline__ uint32_t smem_u32(const void* p) {
    uint32_t a;
    asm("{ .reg .u64 t; cvta.to.shared.u64 t, %1; cvt.u32.u64 %0, t; }"
        : "=r"(a) : "l"(p));
    return a;
}

#define CP16(dst, src) \
    asm volatile("cp.async.cg.shared.global [%0], [%1], 16;" \
                 :: "r"(dst), "l"(src) : "memory")
#define CP_COMMIT() asm volatile("cp.async.commit_group;" ::: "memory")
#define CP_WAIT0()  asm volatile("cp.async.wait_group 0;" ::: "memory")
#define CP_WAIT1()  asm volatile("cp.async.wait_group 1;" ::: "memory")
#define CP_WAIT2()  asm volatile("cp.async.wait_group 2;" ::: "memory")

#define LDSM_X4(r0, r1, r2, r3, addr) \
    asm volatile("ldmatrix.sync.aligned.m8n8.x4.shared.b16 {%0,%1,%2,%3}, [%4];" \
                 : "=r"(r0), "=r"(r1), "=r"(r2), "=r"(r3) : "r"(addr))
#define LDSM_X4T(r0, r1, r2, r3, addr) \
    asm volatile("ldmatrix.sync.aligned.m8n8.x4.trans.shared.b16 {%0,%1,%2,%3}, [%4];" \
                 : "=r"(r0), "=r"(r1), "=r"(r2), "=r"(r3) : "r"(addr))

static __device__ __forceinline__ void mma_f16(float* c, const uint32_t* a,
                                               const uint32_t* b) {
    asm volatile(
        "mma.sync.aligned.m16n8k16.row.col.f32.f16.f16.f32 "
        "{%0,%1,%2,%3}, {%4,%5,%6,%7}, {%8,%9}, {%0,%1,%2,%3};"
        : "+f"(c[0]), "+f"(c[1]), "+f"(c[2]), "+f"(c[3])
        : "r"(a[0]), "r"(a[1]), "r"(a[2]), "r"(a[3]), "r"(b[0]), "r"(b[1]));
}

static __device__ __forceinline__ uint32_t pack_h2(float a, float b) {
    __half2 t = __floats2half2_rn(a, b);
    return *(uint32_t*)&t;
}

static __device__ __forceinline__ uint32_t ex2_h2(uint32_t x) {
    uint32_t y;
    asm("ex2.approx.f16x2 %0, %1;" : "=r"(y) : "r"(x));
    return y;
}

// ---------------- fused weight convert (fp16) + bias pool ------------------
__global__ __launch_bounds__(256) void split_all(const float* __restrict__ Wq,
                                                 const float* __restrict__ Wk,
                                                 const float* __restrict__ Wv,
                                                 const float* __restrict__ Wo,
                                                 const float* __restrict__ W1,
                                                 const float* __restrict__ W2,
                                                 const float* __restrict__ bq,
                                                 const float* __restrict__ bk,
                                                 const float* __restrict__ bv,
                                                 float* __restrict__ bpool,
                                                 __half* __restrict__ w16) {
    const size_t DD4 = (size_t)D_ * D_ / 4;
    const size_t FD4 = (size_t)F_ * D_ / 4;
    const size_t total4 = 4 * DD4 + 2 * FD4;
    size_t gtid = (size_t)blockIdx.x * 256 + threadIdx.x;
    if (gtid < 768) {
        float4 v = (gtid < 256) ? ((const float4*)bq)[gtid]
                 : (gtid < 512) ? ((const float4*)bk)[gtid - 256]
                                : ((const float4*)bv)[gtid - 512];
        ((float4*)bpool)[gtid] = v;
    }
    size_t i = gtid;
    size_t stride = (size_t)gridDim.x * 256;
    for (; i < total4; i += stride) {
        const float4* src;
        size_t j = i;
        if (j < 4 * DD4) {
            int w = (int)(j / DD4);
            j -= (size_t)w * DD4;
            src = (const float4*)(w == 0 ? Wq : w == 1 ? Wk : w == 2 ? Wv : Wo) + j;
        } else {
            j -= 4 * DD4;
            if (j < FD4) src = (const float4*)W1 + j;
            else         src = (const float4*)W2 + (j - FD4);
        }
        float4 v = *src;
        ((__half2*)w16)[i * 2 + 0] = __floats2half2_rn(v.x, v.y);
        ((__half2*)w16)[i * 2 + 1] = __floats2half2_rn(v.z, v.w);
    }
}

// ---------------- LayerNorm -> fp16 single plane ---------------------------
__global__ __launch_bounds__(256) void ln_kernel(const float* __restrict__ x,
                                                 const float* __restrict__ gw,
                                                 const float* __restrict__ bw,
                                                 __half* __restrict__ o16) {
    int row = blockIdx.x;
    int tid = threadIdx.x;
    const float4* xr = (const float4*)(x + (size_t)row * D_);
    float4 v = xr[tid];

    __shared__ float ws[8];
    __shared__ float sstat;
    int lane = tid & 31, wid = tid >> 5;

    float s = v.x + v.y + v.z + v.w;
#pragma unroll
    for (int o = 16; o; o >>= 1) s += __shfl_xor_sync(0xffffffffu, s, o);
    if (lane == 0) ws[wid] = s;
    __syncthreads();
    if (tid == 0) {
        float t = 0.f;
#pragma unroll
        for (int i = 0; i < 8; i++) t += ws[i];
        sstat = t * (1.0f / D_);
    }
    __syncthreads();
    float mu = sstat;

    float4 d;
    d.x = v.x - mu; d.y = v.y - mu; d.z = v.z - mu; d.w = v.w - mu;
    float s2 = d.x*d.x + d.y*d.y + d.z*d.z + d.w*d.w;
#pragma unroll
    for (int o = 16; o; o >>= 1) s2 += __shfl_xor_sync(0xffffffffu, s2, o);
    if (lane == 0) ws[wid] = s2;
    __syncthreads();
    if (tid == 0) {
        float t = 0.f;
#pragma unroll
        for (int i = 0; i < 8; i++) t += ws[i];
        sstat = rsqrtf(t * (1.0f / D_) + 1e-6f);
    }
    __syncthreads();
    float rstd = sstat;

    float4 gv = ((const float4*)gw)[tid];
    float4 bv = ((const float4*)bw)[tid];
    float o0 = d.x * rstd * gv.x + bv.x;
    float o1 = d.y * rstd * gv.y + bv.y;
    float o2 = d.z * rstd * gv.z + bv.z;
    float o3 = d.w * rstd * gv.w + bv.w;

    size_t base = (size_t)row * D_ + tid * 4;
    *(__half2*)(o16 + base)     = __floats2half2_rn(o0, o1);
    *(__half2*)(o16 + base + 2) = __floats2half2_rn(o2, o3);
}

// ---------------- mma.sync fp16 GEMM: C = A @ B^T --------------------------
// Block 128x128, BK=64, 8 warps (2m x 4n), warp tile 64x32, 2 CTAs/SM.
// Stage 32KB: A[16K] B[16K]; 3-stage cp.async pipeline, 1 sync per slab.
// EPI: 1 = fp32 +bias+res; 2 = gelu(+bias) -> fp16;
//      3 = fused QKV epilogue -> fp16 pool (Q scaled 0.125*log2e)
__device__ __forceinline__ float gelu_exact(float x) {
    return 0.5f * x * (1.0f + erff(x * 0.70710678118654752f));
}

#define QSCALE_ 0.18033688011112042f   // 0.125 * log2(e)

#define STAGE_ 32768
#define GEMM_SMEM (3 * STAGE_)

template<int EPI>
__global__ __launch_bounds__(256, 2)
void gemm_tc(const __half* __restrict__ A, const __half* __restrict__ Bm,
             const float* __restrict__ bias, const float* __restrict__ res,
             float* __restrict__ outF, __half* __restrict__ o16,
             int N, int K) {
    extern __shared__ char sm[];
    uint32_t smb = smem_u32(sm);
    int tid = threadIdx.x, lane = tid & 31, warp = tid >> 5;
    int wm = warp & 1;          // rows wm*64
    int wn = warp >> 1;         // cols wn*32
    int bm = blockIdx.y * 128, bn = blockIdx.x * 128;

    const size_t rs = (size_t)K * 2;
    int lrow = tid >> 3;        // 0..31
    int lseg = tid & 7;
    const char* gA = (const char*)A  + (size_t)(bm + lrow) * rs + lseg * 16;
    const char* gB = (const char*)Bm + (size_t)(bn + lrow) * rs + lseg * 16;

    float acc[4][4][4];
#pragma unroll
    for (int i = 0; i < 4; i++)
#pragma unroll
        for (int j = 0; j < 4; j++)
#pragma unroll
            for (int r = 0; r < 4; r++) acc[i][j][r] = 0.f;

    int nk = K >> 6;   // BK = 64

    auto load_slab = [&](int t) {
        uint32_t st = smb + (t % 3) * STAGE_;
        size_t gofs = (size_t)t * 128;
#pragma unroll
        for (int r = 0; r < 4; r++) {
            uint32_t dsw = SWZ((uint32_t)((lrow + r * 32) * 128 + lseg * 16));
            size_t so = (size_t)(r * 32) * rs + gofs;
            CP16(st + dsw,         gA + so);
            CP16(st + 16384 + dsw, gB + so);
        }
        CP_COMMIT();
    };

    load_slab(0);
    load_slab(1);

    int a_row = ((lane >> 3) & 1) * 8 + (lane & 7);
    int a_seg = lane >> 4;
    int b_row = (lane & 7) + ((lane >> 4) << 3);
    int b_seg = (lane >> 3) & 1;

    for (int t = 0; t < nk; t++) {
        if (t + 1 < nk) { CP_WAIT1(); } else { CP_WAIT0(); }
        __syncthreads();
        if (t + 2 < nk) load_slab(t + 2);

        uint32_t sa = smb + (t % 3) * STAGE_;
#pragma unroll
        for (int kk = 0; kk < 4; kk++) {
            uint32_t af[4][4];
#pragma unroll
            for (int mt = 0; mt < 4; mt++) {
                int row = wm * 64 + mt * 16 + a_row;
                uint32_t off = SWZ((uint32_t)(row * 128 + (kk * 2 + a_seg) * 16));
                LDSM_X4(af[mt][0], af[mt][1], af[mt][2], af[mt][3], sa + off);
            }
#pragma unroll
            for (int np = 0; np < 2; np++) {
                int row = wn * 32 + np * 16 + b_row;
                uint32_t off = SWZ((uint32_t)(row * 128 + (kk * 2 + b_seg) * 16));
                uint32_t b4[4];
                LDSM_X4(b4[0], b4[1], b4[2], b4[3], sa + 16384 + off);
#pragma unroll
                for (int mt = 0; mt < 4; mt++) {
                    mma_f16(acc[mt][2 * np],     af[mt], b4);
                    mma_f16(acc[mt][2 * np + 1], af[mt], b4 + 2);
                }
            }
        }
    }

    int r0 = lane >> 2;
    int c0 = (lane & 3) * 2;
#pragma unroll
    for (int mt = 0; mt < 4; mt++) {
#pragma unroll
        for (int nt = 0; nt < 4; nt++) {
            int grow = bm + wm * 64 + mt * 16 + r0;
            int gcol = bn + wn * 32 + nt * 8 + c0;
            float* a4 = acc[mt][nt];
#pragma unroll
            for (int half_ = 0; half_ < 2; half_++) {
                int rr = grow + half_ * 8;
                float v0 = a4[half_ * 2 + 0] + bias[gcol + 0];
                float v1 = a4[half_ * 2 + 1] + bias[gcol + 1];
                if (EPI == 1) {
                    size_t gi = (size_t)rr * N + gcol;
                    float2 rv = *(const float2*)&res[gi];
                    *(float2*)&outF[gi] = make_float2(v0 + rv.x, v1 + rv.y);
                } else if (EPI == 2) {
                    size_t gi = (size_t)rr * N + gcol;
                    *(__half2*)&o16[gi] =
                        __floats2half2_rn(gelu_exact(v0), gelu_exact(v1));
                } else {
                    int w = gcol >> 10;
                    int col = gcol & 1023;
                    float sc = (w == 0) ? QSCALE_ : 1.0f;
                    size_t base = (size_t)w * MD_ + (size_t)rr * D_ + col;
                    *(__half2*)&o16[base] = __floats2half2_rn(v0 * sc, v1 * sc);
                }
            }
        }
    }
}

// ---------------- tensor-core flash attention ------------------------------
// 4 warps x 32 q-rows. Streaming per-16-key block. Softmax via f16x2 exp2;
// row-sums l accumulated by an extra MMA against an all-ones B fragment.
// SMEM: Q 16KB @0; 3 stages of [K|V] 32KB @16384. (112KB -> 2 CTAs/SM)
#define ATT_STAGE 32768
#define ATT_SMEM  (16384 + 3 * ATT_STAGE)

static __device__ __forceinline__ void cp_plane128(uint32_t dst, const char* src,
                                                   int tid) {
#pragma unroll
    for (int i = 0; i < 8; i++) {
        int slot = tid + i * 128;
        int row = slot >> 3, seg = slot & 7;
        CP16(dst + SWZ((uint32_t)(row * 128 + seg * 16)),
             src + (size_t)row * (D_ * 2) + seg * 16);
    }
}

__global__ __launch_bounds__(128, 2)
void attn_tc(const __half* __restrict__ qkv, __half* __restrict__ ctx) {
    extern __shared__ char sm[];
    uint32_t smb = smem_u32(sm);
    int tid = threadIdx.x, lane = tid & 31, warp = tid >> 5;   // 4 warps
    int h = blockIdx.y, b = blockIdx.z;
    int q0 = blockIdx.x * 128;
    size_t bS = (size_t)b * S_;
    size_t hoff = (size_t)h * HD_;

    const __half* q_g = qkv;
    const __half* k_g = qkv + MD_;
    const __half* v_g = qkv + 2 * MD_;

    auto load_kv = [&](int t) {
        uint32_t st = smb + 16384 + (t % 3) * ATT_STAGE;
        size_t ro = (bS + (size_t)t * 128) * D_ + hoff;
        cp_plane128(st,         (const char*)(k_g + ro), tid);
        cp_plane128(st + 16384, (const char*)(v_g + ro), tid);
        CP_COMMIT();
    };

    cp_plane128(smb, (const char*)(q_g + (bS + q0) * D_ + hoff), tid);
    CP_COMMIT();
    load_kv(0);
    CP_WAIT0();
    __syncthreads();

    int a_row = ((lane >> 3) & 1) * 8 + (lane & 7);
    int a_seg = lane >> 4;
    uint32_t qf[2][4][4];   // [row-group][kk][frag]
#pragma unroll
    for (int g = 0; g < 2; g++)
#pragma unroll
        for (int kk = 0; kk < 4; kk++) {
            uint32_t off = SWZ((uint32_t)((warp * 32 + g * 16 + a_row) * 128 +
                                          (kk * 2 + a_seg) * 16));
            LDSM_X4(qf[g][kk][0], qf[g][kk][1], qf[g][kk][2], qf[g][kk][3],
                    smb + off);
        }
    load_kv(1);
    load_kv(2);

    float O[2][8][4];
#pragma unroll
    for (int g = 0; g < 2; g++)
#pragma unroll
        for (int i = 0; i < 8; i++)
#pragma unroll
            for (int j = 0; j < 4; j++) O[g][i][j] = 0.f;
    float lacc[2][4];
#pragma unroll
    for (int g = 0; g < 2; g++)
#pragma unroll
        for (int j = 0; j < 4; j++) lacc[g][j] = 0.f;

    const uint32_t bones[2] = {0x3C003C00u, 0x3C003C00u};   // all ones (fp16)

    int b_row = lane & 7, b_seg = (lane >> 3) & 1, b_t = lane >> 4;
    int v_row = ((lane >> 3) & 1) * 8 + (lane & 7), v_t = lane >> 4;

    for (int t = 0; t < S_ / 128; t++) {
        if (t > 0) {
            if (t + 1 < S_ / 128) { CP_WAIT2(); } else if (t + 0 < S_ / 128) { CP_WAIT0(); }
            __syncthreads();
            if (t + 2 < S_ / 128) load_kv(t + 2);
        }

        uint32_t sa = smb + 16384 + (t % 3) * ATT_STAGE;

#pragma unroll
        for (int tp = 0; tp < 8; tp++) {      // 16-key block
            float s[2][2][4];
#pragma unroll
            for (int g = 0; g < 2; g++)
#pragma unroll
                for (int hh = 0; hh < 2; hh++)
#pragma unroll
                    for (int j = 0; j < 4; j++) s[g][hh][j] = 0.f;

#pragma unroll
            for (int kk = 0; kk < 4; kk++) {
                uint32_t off = SWZ((uint32_t)((tp * 16 + b_t * 8 + b_row) * 128 +
                                              (kk * 2 + b_seg) * 16));
                uint32_t k4[4];
                LDSM_X4(k4[0], k4[1], k4[2], k4[3], sa + off);
                mma_f16(s[0][0], qf[0][kk], k4);
                mma_f16(s[0][1], qf[0][kk], k4 + 2);
                mma_f16(s[1][0], qf[1][kk], k4);
                mma_f16(s[1][1], qf[1][kk], k4 + 2);
            }

            uint32_t AP[2][4];
#pragma unroll
            for (int g = 0; g < 2; g++) {
#pragma unroll
                for (int hh = 0; hh < 2; hh++) {
                    AP[g][hh * 2 + 0] = ex2_h2(pack_h2(s[g][hh][0], s[g][hh][1]));
                    AP[g][hh * 2 + 1] = ex2_h2(pack_h2(s[g][hh][2], s[g][hh][3]));
                }
            }
            mma_f16(lacc[0], AP[0], bones);
            mma_f16(lacc[1], AP[1], bones);

#pragma unroll
            for (int tpv = 0; tpv < 4; tpv++) {
                uint32_t off = SWZ((uint32_t)((tp * 16 + v_row) * 128 +
                                              (2 * tpv + v_t) * 16));
                uint32_t v4[4];
                LDSM_X4T(v4[0], v4[1], v4[2], v4[3], sa + 16384 + off);
                mma_f16(O[0][2 * tpv],     AP[0], v4);
                mma_f16(O[0][2 * tpv + 1], AP[0], v4 + 2);
                mma_f16(O[1][2 * tpv],     AP[1], v4);
                mma_f16(O[1][2 * tpv + 1], AP[1], v4 + 2);
            }
        }
    }

#pragma unroll
    for (int g = 0; g < 2; g++) {
        float inv0 = 1.f / lacc[g][0];
        float inv1 = 1.f / lacc[g][2];

        int rg0 = q0 + warp * 32 + g * 16 + (lane >> 2);
        int cbase = (int)hoff + (lane & 3) * 2;
#pragma unroll
        for (int tp = 0; tp < 8; tp++) {
            int cg = cbase + tp * 8;
            size_t i0 = (bS + rg0) * D_ + cg;
            size_t i1 = (bS + rg0 + 8) * D_ + cg;
            *(__half2*)&ctx[i0] =
                __floats2half2_rn(O[g][tp][0] * inv0, O[g][tp][1] * inv0);
            *(__half2*)&ctx[i1] =
                __floats2half2_rn(O[g][tp][2] * inv1, O[g][tp][3] * inv1);
        }
    }
}

// ---------------- launcher -------------------------------------------------
extern "C" void kernel_launch(void* const* d_in, const int* in_sizes, int n_in,
                              void* d_out, int out_size) {
    const float* x    = (const float*)d_in[0];
    const float* Wq   = (const float*)d_in[1];
    const float* bq   = (const float*)d_in[2];
    const float* Wk   = (const float*)d_in[3];
    const float* bk   = (const float*)d_in[4];
    const float* Wv   = (const float*)d_in[5];
    const float* bv   = (const float*)d_in[6];
    const float* Wo   = (const float*)d_in[7];
    const float* bo   = (const float*)d_in[8];
    const float* W1   = (const float*)d_in[9];
    const float* b1   = (const float*)d_in[10];
    const float* W2   = (const float*)d_in[11];
    const float* b2   = (const float*)d_in[12];
    const float* ln1g = (const float*)d_in[13];
    const float* ln1b = (const float*)d_in[14];
    const float* ln2g = (const float*)d_in[15];
    const float* ln2b = (const float*)d_in[16];
    float* out = (float*)d_out;

    __half *xn, *qkv, *ctx, *h1, *w16;
    float *resb, *bqkv;
    cudaGetSymbolAddress((void**)&xn,   g_xn);
    cudaGetSymbolAddress((void**)&qkv,  g_qkv);
    cudaGetSymbolAddress((void**)&bqkv, g_bqkv);
    cudaGetSymbolAddress((void**)&ctx,  g_ctx);
    cudaGetSymbolAddress((void**)&resb, g_res);
    cudaGetSymbolAddress((void**)&h1,   g_h1);
    cudaGetSymbolAddress((void**)&w16,  g_w);

    const size_t DD = (size_t)D_ * D_;
    const size_t FD = (size_t)F_ * D_;
    __half *wqkv = w16;                  // 3072 x 1024
    __half *wo = w16 + 3 * DD;
    __half *w1 = w16 + 4 * DD;
    __half *w2 = w16 + 4 * DD + FD;

    cudaFuncSetAttribute(gemm_tc<1>, cudaFuncAttributeMaxDynamicSharedMemorySize, GEMM_SMEM);
    cudaFuncSetAttribute(gemm_tc<2>, cudaFuncAttributeMaxDynamicSharedMemorySize, GEMM_SMEM);
    cudaFuncSetAttribute(gemm_tc<3>, cudaFuncAttributeMaxDynamicSharedMemorySize, GEMM_SMEM);
    cudaFuncSetAttribute(attn_tc,    cudaFuncAttributeMaxDynamicSharedMemorySize, ATT_SMEM);

    dim3 gQKV(3072 / 128, M_ / 128);  // (24, 64) = 1536 CTAs
    dim3 gD(D_ / 128, M_ / 128);      // (8, 64)  = 512
    dim3 gF(F_ / 128, M_ / 128);      // (32, 64) = 2048

    // 1) fused weight convert + bias pool
    split_all<<<4096, 256>>>(Wq, Wk, Wv, Wo, W1, W2, bq, bk, bv, bqkv, w16);
    // 2) ln1 -> xn fp16
    ln_kernel<<<M_, 256>>>(x, ln1g, ln1b, xn);
    // 3) fused QKV projection -> fp16 pool (Q scaled log2e/8)
    gemm_tc<3><<<gQKV, 256, GEMM_SMEM>>>(xn, wqkv, bqkv, nullptr,
                                         nullptr, qkv, 3072, D_);
    // 4) attention -> ctx fp16
    attn_tc<<<dim3(S_ / 128, H_, B_), 128, ATT_SMEM>>>(qkv, ctx);
    // 5) O projection + residual(x) -> resb fp32
    gemm_tc<1><<<gD, 256, GEMM_SMEM>>>(ctx, wo, bo, x, resb, nullptr, D_, D_);
    // 6) ln2 -> xn fp16
    ln_kernel<<<M_, 256>>>(resb, ln2g, ln2b, xn);
    // 7) MLP up + exact gelu -> h1 fp16
    gemm_tc<2><<<gF, 256, GEMM_SMEM>>>(xn, w1, b1, nullptr, nullptr, h1, F_, D_);
    // 8) MLP down + residual(resb) -> out fp32
    gemm_tc<1><<<gD, 256, GEMM_SMEM>>>(h1, w2, b2, resb, out, nullptr, D_, F_);
}

// round 16
// speedup vs baseline: 1.0321x; 1.0068x over previous
#include <cuda_runtime.h>
#include <cuda_fp16.h>
#include <cstdint>
#include <math.h>

#define B_  4
#define S_  2048
#define D_  1024
#define H_  16
#define HD_ 64
#define F_  4096
#define M_  (B_ * S_)   // 8192
#define MD_ ((size_t)M_ * D_)

#define SWZ(o) ((o) ^ (((o) >> 3) & 0x70))

// ---------------- scratch (static device globals; no allocation) ----------
__device__ __half g_xn [MD_];
__device__ __half g_qkv[3 * MD_];   // [q|k|v] fp16 single-plane
__device__ float g_bqkv[3 * D_];
__device__ __half g_ctx[MD_];
__device__ float g_res[MD_];
__device__ __half g_h1 [(size_t)M_ * F_];
#define WPOOL_ (4 * (size_t)D_ * D_ + 2 * (size_t)F_ * D_)
__device__ __half g_w[WPOOL_];

// ---------------- PTX helpers ---------------------------------------------
static __device__ __forceinline__ uint32_t smem_u32(const void* p) {
    uint32_t a;
    asm("{ .reg .u64 t; cvta.to.shared.u64 t, %1; cvt.u32.u64 %0, t; }"
        : "=r"(a) : "l"(p));
    return a;
}

#define CP16(dst, src) \
    asm volatile("cp.async.cg.shared.global [%0], [%1], 16;" \
                 :: "r"(dst), "l"(src) : "memory")
#define CP_COMMIT() asm volatile("cp.async.commit_group;" ::: "memory")
#define CP_WAIT0()  asm volatile("cp.async.wait_group 0;" ::: "memory")
#define CP_WAIT1()  asm volatile("cp.async.wait_group 1;" ::: "memory")

#define LDSM_X4(r0, r1, r2, r3, addr) \
    asm volatile("ldmatrix.sync.aligned.m8n8.x4.shared.b16 {%0,%1,%2,%3}, [%4];" \
                 : "=r"(r0), "=r"(r1), "=r"(r2), "=r"(r3) : "r"(addr))
#define LDSM_X4T(r0, r1, r2, r3, addr) \
    asm volatile("ldmatrix.sync.aligned.m8n8.x4.trans.shared.b16 {%0,%1,%2,%3}, [%4];" \
                 : "=r"(r0), "=r"(r1), "=r"(r2), "=r"(r3) : "r"(addr))

static __device__ __forceinline__ void mma_f16(float* c, const uint32_t* a,
                                               const uint32_t* b) {
    asm volatile(
        "mma.sync.aligned.m16n8k16.row.col.f32.f16.f16.f32 "
        "{%0,%1,%2,%3}, {%4,%5,%6,%7}, {%8,%9}, {%0,%1,%2,%3};"
        : "+f"(c[0]), "+f"(c[1]), "+f"(c[2]), "+f"(c[3])
        : "r"(a[0]), "r"(a[1]), "r"(a[2]), "r"(a[3]), "r"(b[0]), "r"(b[1]));
}

static __device__ __forceinline__ uint32_t pack_h2(float a, float b) {
    __half2 t = __floats2half2_rn(a, b);
    return *(uint32_t*)&t;
}

static __device__ __forceinline__ uint32_t ex2_h2(uint32_t x) {
    uint32_t y;
    asm("ex2.approx.f16x2 %0, %1;" : "=r"(y) : "r"(x));
    return y;
}

// ---------------- fused weight convert (fp16) + bias pool ------------------
__global__ __launch_bounds__(256) void split_all(const float* __restrict__ Wq,
                                                 const float* __restrict__ Wk,
                                                 const float* __restrict__ Wv,
                                                 const float* __restrict__ Wo,
                                                 const float* __restrict__ W1,
                                                 const float* __restrict__ W2,
                                                 const float* __restrict__ bq,
                                                 const float* __restrict__ bk,
                                                 const float* __restrict__ bv,
                                                 float* __restrict__ bpool,
                                                 __half* __restrict__ w16) {
    const size_t DD4 = (size_t)D_ * D_ / 4;
    const size_t FD4 = (size_t)F_ * D_ / 4;
    const size_t total4 = 4 * DD4 + 2 * FD4;
    size_t gtid = (size_t)blockIdx.x * 256 + threadIdx.x;
    if (gtid < 768) {
        float4 v = (gtid < 256) ? ((const float4*)bq)[gtid]
                 : (gtid < 512) ? ((const float4*)bk)[gtid - 256]
                                : ((const float4*)bv)[gtid - 512];
        ((float4*)bpool)[gtid] = v;
    }
    size_t i = gtid;
    size_t stride = (size_t)gridDim.x * 256;
    for (; i < total4; i += stride) {
        const float4* src;
        size_t j = i;
        if (j < 4 * DD4) {
            int w = (int)(j / DD4);
            j -= (size_t)w * DD4;
            src = (const float4*)(w == 0 ? Wq : w == 1 ? Wk : w == 2 ? Wv : Wo) + j;
        } else {
            j -= 4 * DD4;
            if (j < FD4) src = (const float4*)W1 + j;
            else         src = (const float4*)W2 + (j - FD4);
        }
        float4 v = *src;
        ((__half2*)w16)[i * 2 + 0] = __floats2half2_rn(v.x, v.y);
        ((__half2*)w16)[i * 2 + 1] = __floats2half2_rn(v.z, v.w);
    }
}

// ---------------- LayerNorm (warp per row) -> fp16 -------------------------
// 8 warps/CTA, 1 row/warp, shfl-only reductions, no smem/syncthreads.
__global__ __launch_bounds__(256) void ln_kernel(const float* __restrict__ x,
                                                 const float* __restrict__ gw,
                                                 const float* __restrict__ bw,
                                                 __half* __restrict__ o16) {
    int warp = threadIdx.x >> 5, lane = threadIdx.x & 31;
    int row = blockIdx.x * 8 + warp;
    const float4* xr = (const float4*)(x + (size_t)row * D_);

    float4 v[8];
    float s = 0.f;
#pragma unroll
    for (int i = 0; i < 8; i++) {
        v[i] = xr[lane + i * 32];
        s += (v[i].x + v[i].y) + (v[i].z + v[i].w);
    }
#pragma unroll
    for (int o = 16; o; o >>= 1) s += __shfl_xor_sync(0xffffffffu, s, o);
    float mu = s * (1.0f / D_);

    float s2 = 0.f;
#pragma unroll
    for (int i = 0; i < 8; i++) {
        v[i].x -= mu; v[i].y -= mu; v[i].z -= mu; v[i].w -= mu;
        s2 += v[i].x * v[i].x + v[i].y * v[i].y
            + v[i].z * v[i].z + v[i].w * v[i].w;
    }
#pragma unroll
    for (int o = 16; o; o >>= 1) s2 += __shfl_xor_sync(0xffffffffu, s2, o);
    float rstd = rsqrtf(s2 * (1.0f / D_) + 1e-6f);

    __half* orow = o16 + (size_t)row * D_;
#pragma unroll
    for (int i = 0; i < 8; i++) {
        int c4 = lane + i * 32;
        float4 gv = ((const float4*)gw)[c4];
        float4 bv = ((const float4*)bw)[c4];
        float o0 = v[i].x * rstd * gv.x + bv.x;
        float o1 = v[i].y * rstd * gv.y + bv.y;
        float o2 = v[i].z * rstd * gv.z + bv.z;
        float o3 = v[i].w * rstd * gv.w + bv.w;
        *(__half2*)(orow + c4 * 4)     = __floats2half2_rn(o0, o1);
        *(__half2*)(orow + c4 * 4 + 2) = __floats2half2_rn(o2, o3);
    }
}

// ---------------- mma.sync fp16 GEMM: C = A @ B^T --------------------------
// Block 128x128, BK=64, 8 warps (2m x 4n), warp tile 64x32, 2 CTAs/SM.
// Stage 32KB: A[16K] B[16K]; 3-stage cp.async pipeline, 1 sync per slab.
// EPI: 1 = fp32 +bias+res; 2 = gelu(+bias) -> fp16;
//      3 = fused QKV epilogue -> fp16 pool (Q scaled 0.125*log2e)
__device__ __forceinline__ float gelu_exact(float x) {
    return 0.5f * x * (1.0f + erff(x * 0.70710678118654752f));
}

#define QSCALE_ 0.18033688011112042f   // 0.125 * log2(e)

#define STAGE_ 32768
#define GEMM_SMEM (3 * STAGE_)

template<int EPI>
__global__ __launch_bounds__(256, 2)
void gemm_tc(const __half* __restrict__ A, const __half* __restrict__ Bm,
             const float* __restrict__ bias, const float* __restrict__ res,
             float* __restrict__ outF, __half* __restrict__ o16,
             int N, int K) {
    extern __shared__ char sm[];
    uint32_t smb = smem_u32(sm);
    int tid = threadIdx.x, lane = tid & 31, warp = tid >> 5;
    int wm = warp & 1;          // rows wm*64
    int wn = warp >> 1;         // cols wn*32
    int bm = blockIdx.y * 128, bn = blockIdx.x * 128;

    const size_t rs = (size_t)K * 2;
    int lrow = tid >> 3;        // 0..31
    int lseg = tid & 7;
    const char* gA = (const char*)A  + (size_t)(bm + lrow) * rs + lseg * 16;
    const char* gB = (const char*)Bm + (size_t)(bn + lrow) * rs + lseg * 16;

    float acc[4][4][4];
#pragma unroll
    for (int i = 0; i < 4; i++)
#pragma unroll
        for (int j = 0; j < 4; j++)
#pragma unroll
            for (int r = 0; r < 4; r++) acc[i][j][r] = 0.f;

    int nk = K >> 6;   // BK = 64

    auto load_slab = [&](int t) {
        uint32_t st = smb + (t % 3) * STAGE_;
        size_t gofs = (size_t)t * 128;
#pragma unroll
        for (int r = 0; r < 4; r++) {
            uint32_t dsw = SWZ((uint32_t)((lrow + r * 32) * 128 + lseg * 16));
            size_t so = (size_t)(r * 32) * rs + gofs;
            CP16(st + dsw,         gA + so);
            CP16(st + 16384 + dsw, gB + so);
        }
        CP_COMMIT();
    };

    load_slab(0);
    load_slab(1);

    int a_row = ((lane >> 3) & 1) * 8 + (lane & 7);
    int a_seg = lane >> 4;
    int b_row = (lane & 7) + ((lane >> 4) << 3);
    int b_seg = (lane >> 3) & 1;

    for (int t = 0; t < nk; t++) {
        if (t + 1 < nk) { CP_WAIT1(); } else { CP_WAIT0(); }
        __syncthreads();
        if (t + 2 < nk) load_slab(t + 2);

        uint32_t sa = smb + (t % 3) * STAGE_;
#pragma unroll
        for (int kk = 0; kk < 4; kk++) {
            uint32_t af[4][4];
#pragma unroll
            for (int mt = 0; mt < 4; mt++) {
                int row = wm * 64 + mt * 16 + a_row;
                uint32_t off = SWZ((uint32_t)(row * 128 + (kk * 2 + a_seg) * 16));
                LDSM_X4(af[mt][0], af[mt][1], af[mt][2], af[mt][3], sa + off);
            }
#pragma unroll
            for (int np = 0; np < 2; np++) {
                int row = wn * 32 + np * 16 + b_row;
                uint32_t off = SWZ((uint32_t)(row * 128 + (kk * 2 + b_seg) * 16));
                uint32_t b4[4];
                LDSM_X4(b4[0], b4[1], b4[2], b4[3], sa + 16384 + off);
#pragma unroll
                for (int mt = 0; mt < 4; mt++) {
                    mma_f16(acc[mt][2 * np],     af[mt], b4);
                    mma_f16(acc[mt][2 * np + 1], af[mt], b4 + 2);
                }
            }
        }
    }

    int r0 = lane >> 2;
    int c0 = (lane & 3) * 2;
#pragma unroll
    for (int mt = 0; mt < 4; mt++) {
#pragma unroll
        for (int nt = 0; nt < 4; nt++) {
            int grow = bm + wm * 64 + mt * 16 + r0;
            int gcol = bn + wn * 32 + nt * 8 + c0;
            float* a4 = acc[mt][nt];
#pragma unroll
            for (int half_ = 0; half_ < 2; half_++) {
                int rr = grow + half_ * 8;
                float v0 = a4[half_ * 2 + 0] + bias[gcol + 0];
                float v1 = a4[half_ * 2 + 1] + bias[gcol + 1];
                if (EPI == 1) {
                    size_t gi = (size_t)rr * N + gcol;
                    float2 rv = *(const float2*)&res[gi];
                    *(float2*)&outF[gi] = make_float2(v0 + rv.x, v1 + rv.y);
                } else if (EPI == 2) {
                    size_t gi = (size_t)rr * N + gcol;
                    *(__half2*)&o16[gi] =
                        __floats2half2_rn(gelu_exact(v0), gelu_exact(v1));
                } else {
                    int w = gcol >> 10;
                    int col = gcol & 1023;
                    float sc = (w == 0) ? QSCALE_ : 1.0f;
                    size_t base = (size_t)w * MD_ + (size_t)rr * D_ + col;
                    *(__half2*)&o16[base] = __floats2half2_rn(v0 * sc, v1 * sc);
                }
            }
        }
    }
}

// ---------------- tensor-core flash attention ------------------------------
// 4 warps x 32 q-rows. Streaming per-16-key block. Softmax via f16x2 exp2;
// row-sums l accumulated by an extra MMA against an all-ones B fragment.
// SMEM: Q 16KB @0; 2 stages of [K|V] 32KB @16384. (80KB -> 2 CTAs/SM)
#define ATT_STAGE 32768
#define ATT_SMEM  (16384 + 2 * ATT_STAGE)

static __device__ __forceinline__ void cp_plane128(uint32_t dst, const char* src,
                                                   int tid) {
#pragma unroll
    for (int i = 0; i < 8; i++) {
        int slot = tid + i * 128;
        int row = slot >> 3, seg = slot & 7;
        CP16(dst + SWZ((uint32_t)(row * 128 + seg * 16)),
             src + (size_t)row * (D_ * 2) + seg * 16);
    }
}

__global__ __launch_bounds__(128, 2)
void attn_tc(const __half* __restrict__ qkv, __half* __restrict__ ctx) {
    extern __shared__ char sm[];
    uint32_t smb = smem_u32(sm);
    int tid = threadIdx.x, lane = tid & 31, warp = tid >> 5;   // 4 warps
    int h = blockIdx.y, b = blockIdx.z;
    int q0 = blockIdx.x * 128;
    size_t bS = (size_t)b * S_;
    size_t hoff = (size_t)h * HD_;

    const __half* q_g = qkv;
    const __half* k_g = qkv + MD_;
    const __half* v_g = qkv + 2 * MD_;

    auto load_kv = [&](int t) {
        uint32_t st = smb + 16384 + (t & 1) * ATT_STAGE;
        size_t ro = (bS + (size_t)t * 128) * D_ + hoff;
        cp_plane128(st,         (const char*)(k_g + ro), tid);
        cp_plane128(st + 16384, (const char*)(v_g + ro), tid);
        CP_COMMIT();
    };

    cp_plane128(smb, (const char*)(q_g + (bS + q0) * D_ + hoff), tid);
    CP_COMMIT();
    load_kv(0);
    CP_WAIT0();
    __syncthreads();

    int a_row = ((lane >> 3) & 1) * 8 + (lane & 7);
    int a_seg = lane >> 4;
    uint32_t qf[2][4][4];   // [row-group][kk][frag]
#pragma unroll
    for (int g = 0; g < 2; g++)
#pragma unroll
        for (int kk = 0; kk < 4; kk++) {
            uint32_t off = SWZ((uint32_t)((warp * 32 + g * 16 + a_row) * 128 +
                                          (kk * 2 + a_seg) * 16));
            LDSM_X4(qf[g][kk][0], qf[g][kk][1], qf[g][kk][2], qf[g][kk][3],
                    smb + off);
        }
    load_kv(1);

    float O[2][8][4];
#pragma unroll
    for (int g = 0; g < 2; g++)
#pragma unroll
        for (int i = 0; i < 8; i++)
#pragma unroll
            for (int j = 0; j < 4; j++) O[g][i][j] = 0.f;
    float lacc[2][4];
#pragma unroll
    for (int g = 0; g < 2; g++)
#pragma unroll
        for (int j = 0; j < 4; j++) lacc[g][j] = 0.f;

    const uint32_t bones[2] = {0x3C003C00u, 0x3C003C00u};   // all ones (fp16)

    int b_row = lane & 7, b_seg = (lane >> 3) & 1, b_t = lane >> 4;
    int v_row = ((lane >> 3) & 1) * 8 + (lane & 7), v_t = lane >> 4;

    for (int t = 0; t < S_ / 128; t++) {
        if (t > 0) {
            CP_WAIT0();
            __syncthreads();
            if (t + 1 < S_ / 128) load_kv(t + 1);
        }

        uint32_t sa = smb + 16384 + (t & 1) * ATT_STAGE;

#pragma unroll
        for (int tp = 0; tp < 8; tp++) {      // 16-key block
            float s[2][2][4];
#pragma unroll
            for (int g = 0; g < 2; g++)
#pragma unroll
                for (int hh = 0; hh < 2; hh++)
#pragma unroll
                    for (int j = 0; j < 4; j++) s[g][hh][j] = 0.f;

#pragma unroll
            for (int kk = 0; kk < 4; kk++) {
                uint32_t off = SWZ((uint32_t)((tp * 16 + b_t * 8 + b_row) * 128 +
                                              (kk * 2 + b_seg) * 16));
                uint32_t k4[4];
                LDSM_X4(k4[0], k4[1], k4[2], k4[3], sa + off);
                mma_f16(s[0][0], qf[0][kk], k4);
                mma_f16(s[0][1], qf[0][kk], k4 + 2);
                mma_f16(s[1][0], qf[1][kk], k4);
                mma_f16(s[1][1], qf[1][kk], k4 + 2);
            }

            uint32_t AP[2][4];
#pragma unroll
            for (int g = 0; g < 2; g++) {
#pragma unroll
                for (int hh = 0; hh < 2; hh++) {
                    AP[g][hh * 2 + 0] = ex2_h2(pack_h2(s[g][hh][0], s[g][hh][1]));
                    AP[g][hh * 2 + 1] = ex2_h2(pack_h2(s[g][hh][2], s[g][hh][3]));
                }
            }
            mma_f16(lacc[0], AP[0], bones);
            mma_f16(lacc[1], AP[1], bones);

#pragma unroll
            for (int tpv = 0; tpv < 4; tpv++) {
                uint32_t off = SWZ((uint32_t)((tp * 16 + v_row) * 128 +
                                              (2 * tpv + v_t) * 16));
                uint32_t v4[4];
                LDSM_X4T(v4[0], v4[1], v4[2], v4[3], sa + 16384 + off);
                mma_f16(O[0][2 * tpv],     AP[0], v4);
                mma_f16(O[0][2 * tpv + 1], AP[0], v4 + 2);
                mma_f16(O[1][2 * tpv],     AP[1], v4);
                mma_f16(O[1][2 * tpv + 1], AP[1], v4 + 2);
            }
        }
    }

#pragma unroll
    for (int g = 0; g < 2; g++) {
        float inv0 = 1.f / lacc[g][0];
        float inv1 = 1.f / lacc[g][2];

        int rg0 = q0 + warp * 32 + g * 16 + (lane >> 2);
        int cbase = (int)hoff + (lane & 3) * 2;
#pragma unroll
        for (int tp = 0; tp < 8; tp++) {
            int cg = cbase + tp * 8;
            size_t i0 = (bS + rg0) * D_ + cg;
            size_t i1 = (bS + rg0 + 8) * D_ + cg;
            *(__half2*)&ctx[i0] =
                __floats2half2_rn(O[g][tp][0] * inv0, O[g][tp][1] * inv0);
            *(__half2*)&ctx[i1] =
                __floats2half2_rn(O[g][tp][2] * inv1, O[g][tp][3] * inv1);
        }
    }
}

// ---------------- launcher -------------------------------------------------
extern "C" void kernel_launch(void* const* d_in, const int* in_sizes, int n_in,
                              void* d_out, int out_size) {
    const float* x    = (const float*)d_in[0];
    const float* Wq   = (const float*)d_in[1];
    const float* bq   = (const float*)d_in[2];
    const float* Wk   = (const float*)d_in[3];
    const float* bk   = (const float*)d_in[4];
    const float* Wv   = (const float*)d_in[5];
    const float* bv   = (const float*)d_in[6];
    const float* Wo   = (const float*)d_in[7];
    const float* bo   = (const float*)d_in[8];
    const float* W1   = (const float*)d_in[9];
    const float* b1   = (const float*)d_in[10];
    const float* W2   = (const float*)d_in[11];
    const float* b2   = (const float*)d_in[12];
    const float* ln1g = (const float*)d_in[13];
    const float* ln1b = (const float*)d_in[14];
    const float* ln2g = (const float*)d_in[15];
    const float* ln2b = (const float*)d_in[16];
    float* out = (float*)d_out;

    __half *xn, *qkv, *ctx, *h1, *w16;
    float *resb, *bqkv;
    cudaGetSymbolAddress((void**)&xn,   g_xn);
    cudaGetSymbolAddress((void**)&qkv,  g_qkv);
    cudaGetSymbolAddress((void**)&bqkv, g_bqkv);
    cudaGetSymbolAddress((void**)&ctx,  g_ctx);
    cudaGetSymbolAddress((void**)&resb, g_res);
    cudaGetSymbolAddress((void**)&h1,   g_h1);
    cudaGetSymbolAddress((void**)&w16,  g_w);

    const size_t DD = (size_t)D_ * D_;
    const size_t FD = (size_t)F_ * D_;
    __half *wqkv = w16;                  // 3072 x 1024
    __half *wo = w16 + 3 * DD;
    __half *w1 = w16 + 4 * DD;
    __half *w2 = w16 + 4 * DD + FD;

    cudaFuncSetAttribute(gemm_tc<1>, cudaFuncAttributeMaxDynamicSharedMemorySize, GEMM_SMEM);
    cudaFuncSetAttribute(gemm_tc<2>, cudaFuncAttributeMaxDynamicSharedMemorySize, GEMM_SMEM);
    cudaFuncSetAttribute(gemm_tc<3>, cudaFuncAttributeMaxDynamicSharedMemorySize, GEMM_SMEM);
    cudaFuncSetAttribute(attn_tc,    cudaFuncAttributeMaxDynamicSharedMemorySize, ATT_SMEM);

    dim3 gQKV(3072 / 128, M_ / 128);  // (24, 64) = 1536 CTAs
    dim3 gD(D_ / 128, M_ / 128);      // (8, 64)  = 512
    dim3 gF(F_ / 128, M_ / 128);      // (32, 64) = 2048

    // 1) fused weight convert + bias pool
    split_all<<<4096, 256>>>(Wq, Wk, Wv, Wo, W1, W2, bq, bk, bv, bqkv, w16);
    // 2) ln1 -> xn fp16 (warp-per-row)
    ln_kernel<<<M_ / 8, 256>>>(x, ln1g, ln1b, xn);
    // 3) fused QKV projection -> fp16 pool (Q scaled log2e/8)
    gemm_tc<3><<<gQKV, 256, GEMM_SMEM>>>(xn, wqkv, bqkv, nullptr,
                                         nullptr, qkv, 3072, D_);
    // 4) attention -> ctx fp16
    attn_tc<<<dim3(S_ / 128, H_, B_), 128, ATT_SMEM>>>(qkv, ctx);
    // 5) O projection + residual(x) -> resb fp32
    gemm_tc<1><<<gD, 256, GEMM_SMEM>>>(ctx, wo, bo, x, resb, nullptr, D_, D_);
    // 6) ln2 -> xn fp16 (warp-per-row)
    ln_kernel<<<M_ / 8, 256>>>(resb, ln2g, ln2b, xn);
    // 7) MLP up + exact gelu -> h1 fp16
    gemm_tc<2><<<gF, 256, GEMM_SMEM>>>(xn, w1, b1, nullptr, nullptr, h1, F_, D_);
    // 8) MLP down + residual(resb) -> out fp32
    gemm_tc<1><<<gD, 256, GEMM_SMEM>>>(h1, w2, b2, resb, out, nullptr, D_, F_);
}